// round 13
// baseline (speedup 1.0000x reference)
#include <cuda_runtime.h>
#include <math_constants.h>

// Problem constants (B=2, H=16, S=2048, D=64)
#define S_LEN 2048
#define D_DIM 64
#define BH    32
#define BT    64              // tile size (rows & cols)
#define NT    (S_LEN / BT)    // 32 tiles along sequence
#define LDP   68              // smem pitch in floats (keeps 16B alignment, skews banks)

#define SMEM_FLOATS (4 * D_DIM * LDP + NT * BT)   // Qs,Ks,Vs,Ps + m-history
#define SMEM_BYTES  (SMEM_FLOATS * 4)

typedef unsigned long long u64;

// ---------- packed f32x2 helpers (Blackwell sm_103a) ----------
__device__ __forceinline__ u64 pk(float lo, float hi) {
    u64 r;
    asm("mov.b64 %0, {%1,%2};" : "=l"(r) : "f"(lo), "f"(hi));
    return r;
}
__device__ __forceinline__ void upk(u64 v, float& lo, float& hi) {
    asm("mov.b64 {%0,%1}, %2;" : "=f"(lo), "=f"(hi) : "l"(v));
}
__device__ __forceinline__ u64 ffma2(u64 a, u64 b, u64 c) {
    u64 d;
    asm("fma.rn.f32x2 %0, %1, %2, %3;" : "=l"(d) : "l"(a), "l"(b), "l"(c));
    return d;
}
__device__ __forceinline__ u64 fmul2(u64 a, u64 b) {
    u64 d;
    asm("mul.rn.f32x2 %0, %1, %2;" : "=l"(d) : "l"(a), "l"(b));
    return d;
}

// Load a 64x64 fp32 tile from gmem (row-major, row stride D_DIM) into smem
// TRANSPOSED to d-major layout: sm[d*LDP + row].
__device__ __forceinline__ void load_tileT(const float* __restrict__ g, float* sm, int tid) {
#pragma unroll
    for (int it = 0; it < 4; it++) {
        int idx = tid + 256 * it;
        int row = idx >> 4;
        int dq  = (idx & 15) << 2;
        float4 v = *(const float4*)(g + row * D_DIM + dq);
        sm[(dq + 0) * LDP + row] = v.x;
        sm[(dq + 1) * LDP + row] = v.y;
        sm[(dq + 2) * LDP + row] = v.z;
        sm[(dq + 3) * LDP + row] = v.w;
    }
}

// Load a 64x64 fp32 tile natural (row-major) into smem: sm[row*LDP + d]
__device__ __forceinline__ void load_tile(const float* __restrict__ g, float* sm, int tid) {
#pragma unroll
    for (int it = 0; it < 4; it++) {
        int idx = tid + 256 * it;
        int row = idx >> 4;
        int dq  = (idx & 15) << 2;
        *(float4*)(sm + row * LDP + dq) = *(const float4*)(g + row * D_DIM + dq);
    }
}

__global__ void __launch_bounds__(256, 2)
sdpa_causal_kernel(const float* __restrict__ Qg, const float* __restrict__ Kg,
                   const float* __restrict__ Vg, float* __restrict__ Og,
                   float* __restrict__ Wg)
{
    extern __shared__ float sm[];
    float* Qs = sm;                      // [D_DIM][LDP], d-major
    float* Ks = Qs + D_DIM * LDP;        // [D_DIM][LDP], d-major
    float* Vs = Ks + D_DIM * LDP;        // [BT][LDP],   row(j)-major
    float* Ps = Vs + BT * LDP;           // [BT][LDP],   j-major (p transposed)
    float* mh = Ps + BT * LDP;           // [NT][BT]     running-max history

    const int qt  = blockIdx.x;          // q-tile index 0..31
    const int bh  = blockIdx.y;          // fused (batch, head)
    const int tid = threadIdx.x;
    const int tr  = tid >> 4;            // 0..15  (query-row group)
    const int tc  = tid & 15;            // 0..15  (key-col / out-dim group)
    const int i0  = tr * 4;
    const int j0  = tc * 4;

    const float* Qb = Qg + (size_t)bh * S_LEN * D_DIM + (size_t)qt * BT * D_DIM;
    const float* Kb = Kg + (size_t)bh * S_LEN * D_DIM;
    const float* Vb = Vg + (size_t)bh * S_LEN * D_DIM;
    float*       Ob = Og + (size_t)bh * S_LEN * D_DIM + (size_t)qt * BT * D_DIM;
    float*       Wb = Wg + (size_t)bh * S_LEN * S_LEN;

    load_tileT(Qb, Qs, tid);

    float m_r[4], l_r[4];
    u64 Oac[2][4];                       // row-pair packed output accumulators
#pragma unroll
    for (int r = 0; r < 4; r++) { m_r[r] = -CUDART_INF_F; l_r[r] = 0.f; }
#pragma unroll
    for (int rp = 0; rp < 2; rp++)
#pragma unroll
        for (int c = 0; c < 4; c++) Oac[rp][c] = 0ull;

    float p[4][4];                       // exp(scores) for current tile

    for (int jt = 0; jt <= qt; jt++) {
        __syncthreads();                 // previous PV finished reading Ks/Vs/Ps
        load_tileT(Kb + (size_t)jt * BT * D_DIM, Ks, tid);
        load_tile (Vb + (size_t)jt * BT * D_DIM, Vs, tid);
        __syncthreads();

        // ---- QK^T gemm: acc[rp][c] holds packed (row i0+2rp, i0+2rp+1) ----
        u64 acc[2][4];
#pragma unroll
        for (int rp = 0; rp < 2; rp++)
#pragma unroll
            for (int c = 0; c < 4; c++) acc[rp][c] = 0ull;

#pragma unroll 16
        for (int d = 0; d < D_DIM; d++) {
            ulonglong2 a = *(const ulonglong2*)(Qs + d * LDP + i0);  // rows (i0,i0+1),(i0+2,i0+3)
            float4     b = *(const float4*)(Ks + d * LDP + j0);
            u64 b0 = pk(b.x, b.x), b1 = pk(b.y, b.y), b2 = pk(b.z, b.z), b3 = pk(b.w, b.w);
            acc[0][0] = ffma2(a.x, b0, acc[0][0]);
            acc[0][1] = ffma2(a.x, b1, acc[0][1]);
            acc[0][2] = ffma2(a.x, b2, acc[0][2]);
            acc[0][3] = ffma2(a.x, b3, acc[0][3]);
            acc[1][0] = ffma2(a.y, b0, acc[1][0]);
            acc[1][1] = ffma2(a.y, b1, acc[1][1]);
            acc[1][2] = ffma2(a.y, b2, acc[1][2]);
            acc[1][3] = ffma2(a.y, b3, acc[1][3]);
        }

        // unpack + scale (1/sqrt(64) = 0.125 exactly)
#pragma unroll
        for (int c = 0; c < 4; c++) {
            upk(acc[0][c], p[0][c], p[1][c]);
            upk(acc[1][c], p[2][c], p[3][c]);
        }
#pragma unroll
        for (int r = 0; r < 4; r++)
#pragma unroll
            for (int c = 0; c < 4; c++) p[r][c] *= 0.125f;

        // causal mask on the diagonal tile
        if (jt == qt) {
#pragma unroll
            for (int r = 0; r < 4; r++)
#pragma unroll
                for (int c = 0; c < 4; c++)
                    if (j0 + c > i0 + r) p[r][c] = -CUDART_INF_F;
        }

        float mnew[4], alpha[4];
#pragma unroll
        for (int r = 0; r < 4; r++) {
            float tm = fmaxf(fmaxf(p[r][0], p[r][1]), fmaxf(p[r][2], p[r][3]));
#pragma unroll
            for (int off = 1; off < 16; off <<= 1)
                tm = fmaxf(tm, __shfl_xor_sync(0xffffffffu, tm, off));
            mnew[r]  = fmaxf(m_r[r], tm);
            alpha[r] = __expf(m_r[r] - mnew[r]);
            float rs = 0.f;
#pragma unroll
            for (int c = 0; c < 4; c++) {
                p[r][c] = __expf(p[r][c] - mnew[r]);
                rs += p[r][c];
            }
#pragma unroll
            for (int off = 1; off < 16; off <<= 1)
                rs += __shfl_xor_sync(0xffffffffu, rs, off);
            l_r[r] = l_r[r] * alpha[r] + rs;
            m_r[r] = mnew[r];
        }
        {
            u64 av0 = pk(alpha[0], alpha[1]);
            u64 av1 = pk(alpha[2], alpha[3]);
#pragma unroll
            for (int c = 0; c < 4; c++) {
                Oac[0][c] = fmul2(av0, Oac[0][c]);
                Oac[1][c] = fmul2(av1, Oac[1][c]);
            }
        }

        // record running max for later fixup (uniform across tc; one writer)
        if (tc == 0) {
#pragma unroll
            for (int r = 0; r < 4; r++) mh[jt * BT + i0 + r] = mnew[r];
        }

        // stash p (transposed, j-major) for the PV gemm
#pragma unroll
        for (int r = 0; r < 4; r++)
#pragma unroll
            for (int c = 0; c < 4; c++)
                Ps[(j0 + c) * LDP + i0 + r] = p[r][c];

        // write UNNORMALIZED p for non-diagonal tiles (fixed up in epilogue)
        if (jt < qt) {
#pragma unroll
            for (int r = 0; r < 4; r++) {
                *(float4*)(Wb + (size_t)(qt * BT + i0 + r) * S_LEN + jt * BT + j0) =
                    make_float4(p[r][0], p[r][1], p[r][2], p[r][3]);
            }
        }

        __syncthreads();                 // Ps visible to all

        // ---- PV gemm: O[i][dd] += p[i][j] * V[j][dd] ----
#pragma unroll 16
        for (int j = 0; j < BT; j++) {
            ulonglong2 a = *(const ulonglong2*)(Ps + j * LDP + i0);  // p row-pairs at col j
            float4     b = *(const float4*)(Vs + j * LDP + j0);
            u64 b0 = pk(b.x, b.x), b1 = pk(b.y, b.y), b2 = pk(b.z, b.z), b3 = pk(b.w, b.w);
            Oac[0][0] = ffma2(a.x, b0, Oac[0][0]);
            Oac[0][1] = ffma2(a.x, b1, Oac[0][1]);
            Oac[0][2] = ffma2(a.x, b2, Oac[0][2]);
            Oac[0][3] = ffma2(a.x, b3, Oac[0][3]);
            Oac[1][0] = ffma2(a.y, b0, Oac[1][0]);
            Oac[1][1] = ffma2(a.y, b1, Oac[1][1]);
            Oac[1][2] = ffma2(a.y, b2, Oac[1][2]);
            Oac[1][3] = ffma2(a.y, b3, Oac[1][3]);
        }
    }

    float invl[4];
#pragma unroll
    for (int r = 0; r < 4; r++) invl[r] = 1.0f / l_r[r];

    // diagonal tile: p still holds jt==qt values, m there == m_final -> just /l
#pragma unroll
    for (int r = 0; r < 4; r++) {
        *(float4*)(Wb + (size_t)(qt * BT + i0 + r) * S_LEN + qt * BT + j0) =
            make_float4(p[r][0] * invl[r], p[r][1] * invl[r],
                        p[r][2] * invl[r], p[r][3] * invl[r]);
    }

    // attention output
    {
        float o[4][4];
#pragma unroll
        for (int c = 0; c < 4; c++) {
            upk(Oac[0][c], o[0][c], o[1][c]);
            upk(Oac[1][c], o[2][c], o[3][c]);
        }
#pragma unroll
        for (int r = 0; r < 4; r++) {
            *(float4*)(Ob + (i0 + r) * D_DIM + j0) =
                make_float4(o[r][0] * invl[r], o[r][1] * invl[r],
                            o[r][2] * invl[r], o[r][3] * invl[r]);
        }
    }

    __syncthreads();   // all mh writes visible for cross-thread reads below

    // fixup: rescale earlier tiles by exp(m_tile - m_final) / l
    for (int jt = 0; jt < qt; jt++) {
#pragma unroll
        for (int r = 0; r < 4; r++) {
            float f = __expf(mh[jt * BT + i0 + r] - m_r[r]) * invl[r];
            float* addr = Wb + (size_t)(qt * BT + i0 + r) * S_LEN + jt * BT + j0;
            float4 w = *(float4*)addr;
            w.x *= f; w.y *= f; w.z *= f; w.w *= f;
            *(float4*)addr = w;
        }
    }

    // zero-fill strict upper-triangle tiles
    float4 z = make_float4(0.f, 0.f, 0.f, 0.f);
    for (int jt = qt + 1; jt < NT; jt++) {
#pragma unroll
        for (int r = 0; r < 4; r++)
            *(float4*)(Wb + (size_t)(qt * BT + i0 + r) * S_LEN + jt * BT + j0) = z;
    }
}

extern "C" void kernel_launch(void* const* d_in, const int* in_sizes, int n_in,
                              void* d_out, int out_size) {
    (void)in_sizes; (void)n_in; (void)out_size;
    const float* q = (const float*)d_in[0];
    const float* k = (const float*)d_in[1];
    const float* v = (const float*)d_in[2];
    // d_in[3] is the mask (tril ones) — causal structure applied analytically.

    float* out = (float*)d_out;
    float* Og  = out;                                   // [B,H,S,D] = 4,194,304 floats
    float* Wg  = out + (size_t)BH * S_LEN * D_DIM;      // [B,H,S,S] follows

    cudaFuncSetAttribute(sdpa_causal_kernel,
                         cudaFuncAttributeMaxDynamicSharedMemorySize, SMEM_BYTES);

    dim3 grid(NT, BH);
    sdpa_causal_kernel<<<grid, 256, SMEM_BYTES>>>(q, k, v, Og, Wg);
}

// round 14
// speedup vs baseline: 1.3842x; 1.3842x over previous
#include <cuda_runtime.h>
#include <math_constants.h>

// Problem constants (B=2, H=16, S=2048, D=64)
#define S_LEN 2048
#define D_DIM 64
#define BH    32
#define BT    64              // tile size (rows & cols)
#define NT    (S_LEN / BT)    // 32 tiles along sequence
#define LDP   68              // smem pitch in floats (keeps 16B alignment, skews banks)

#define SMEM_FLOATS (4 * D_DIM * LDP + NT * BT)   // Qs,Ks,Vs,Ps + m-history
#define SMEM_BYTES  (SMEM_FLOATS * 4)

typedef unsigned long long u64;

// ---------- packed f32x2 helpers (Blackwell sm_103a) ----------
__device__ __forceinline__ u64 pk(float lo, float hi) {
    u64 r;
    asm("mov.b64 %0, {%1,%2};" : "=l"(r) : "f"(lo), "f"(hi));
    return r;
}
__device__ __forceinline__ void upk(u64 v, float& lo, float& hi) {
    asm("mov.b64 {%0,%1}, %2;" : "=f"(lo), "=f"(hi) : "l"(v));
}
__device__ __forceinline__ u64 ffma2(u64 a, u64 b, u64 c) {
    u64 d;
    asm("fma.rn.f32x2 %0, %1, %2, %3;" : "=l"(d) : "l"(a), "l"(b), "l"(c));
    return d;
}
__device__ __forceinline__ u64 fmul2(u64 a, u64 b) {
    u64 d;
    asm("mul.rn.f32x2 %0, %1, %2;" : "=l"(d) : "l"(a), "l"(b));
    return d;
}

// Load a 64x64 fp32 tile from gmem (row-major, row stride D_DIM) into smem
// TRANSPOSED to d-major layout: sm[d*LDP + row].
__device__ __forceinline__ void load_tileT(const float* __restrict__ g, float* sm, int tid) {
#pragma unroll
    for (int it = 0; it < 4; it++) {
        int idx = tid + 256 * it;
        int row = idx >> 4;
        int dq  = (idx & 15) << 2;
        float4 v = *(const float4*)(g + row * D_DIM + dq);
        sm[(dq + 0) * LDP + row] = v.x;
        sm[(dq + 1) * LDP + row] = v.y;
        sm[(dq + 2) * LDP + row] = v.z;
        sm[(dq + 3) * LDP + row] = v.w;
    }
}

// Load a 64x64 fp32 tile natural (row-major) into smem: sm[row*LDP + d]
__device__ __forceinline__ void load_tile(const float* __restrict__ g, float* sm, int tid) {
#pragma unroll
    for (int it = 0; it < 4; it++) {
        int idx = tid + 256 * it;
        int row = idx >> 4;
        int dq  = (idx & 15) << 2;
        *(float4*)(sm + row * LDP + dq) = *(const float4*)(g + row * D_DIM + dq);
    }
}

__global__ void __launch_bounds__(256, 2)
sdpa_causal_kernel(const float* __restrict__ Qg, const float* __restrict__ Kg,
                   const float* __restrict__ Vg, float* __restrict__ Og,
                   float* __restrict__ Wg)
{
    extern __shared__ float sm[];
    float* Qs = sm;                      // [D_DIM][LDP], d-major
    float* Ks = Qs + D_DIM * LDP;        // [D_DIM][LDP], d-major
    float* Vs = Ks + D_DIM * LDP;        // [BT][LDP],   row(j)-major
    float* Ps = Vs + BT * LDP;           // [BT][LDP],   j-major (p transposed)
    float* mh = Ps + BT * LDP;           // [NT][BT]     running-max history

    const int qt  = blockIdx.x;          // q-tile index 0..31
    const int bh  = blockIdx.y;          // fused (batch, head)
    const int tid = threadIdx.x;
    const int tr  = tid >> 4;            // 0..15  (query-row group)
    const int tc  = tid & 15;            // 0..15  (key-col / out-dim group)
    const int i0  = tr * 4;
    const int j0  = tc * 4;

    const float* Qb = Qg + (size_t)bh * S_LEN * D_DIM + (size_t)qt * BT * D_DIM;
    const float* Kb = Kg + (size_t)bh * S_LEN * D_DIM;
    const float* Vb = Vg + (size_t)bh * S_LEN * D_DIM;
    float*       Ob = Og + (size_t)bh * S_LEN * D_DIM + (size_t)qt * BT * D_DIM;
    float*       Wb = Wg + (size_t)bh * S_LEN * S_LEN;

    load_tileT(Qb, Qs, tid);

    float m_r[4], l_r[4];
    u64 Oac[2][4];                       // row-pair packed output accumulators
#pragma unroll
    for (int r = 0; r < 4; r++) { m_r[r] = -CUDART_INF_F; l_r[r] = 0.f; }
#pragma unroll
    for (int rp = 0; rp < 2; rp++)
#pragma unroll
        for (int c = 0; c < 4; c++) Oac[rp][c] = 0ull;

    float p[4][4];                       // exp(scores) for current tile

    for (int jt = 0; jt <= qt; jt++) {
        __syncthreads();                 // previous PV finished reading Ks/Vs/Ps
        load_tileT(Kb + (size_t)jt * BT * D_DIM, Ks, tid);
        load_tile (Vb + (size_t)jt * BT * D_DIM, Vs, tid);
        __syncthreads();

        // ---- QK^T gemm: acc[rp][c] holds packed (row i0+2rp, i0+2rp+1) ----
        u64 acc[2][4];
#pragma unroll
        for (int rp = 0; rp < 2; rp++)
#pragma unroll
            for (int c = 0; c < 4; c++) acc[rp][c] = 0ull;

#pragma unroll 16
        for (int d = 0; d < D_DIM; d++) {
            ulonglong2 a = *(const ulonglong2*)(Qs + d * LDP + i0);  // rows (i0,i0+1),(i0+2,i0+3)
            float4     b = *(const float4*)(Ks + d * LDP + j0);
            u64 b0 = pk(b.x, b.x), b1 = pk(b.y, b.y), b2 = pk(b.z, b.z), b3 = pk(b.w, b.w);
            acc[0][0] = ffma2(a.x, b0, acc[0][0]);
            acc[0][1] = ffma2(a.x, b1, acc[0][1]);
            acc[0][2] = ffma2(a.x, b2, acc[0][2]);
            acc[0][3] = ffma2(a.x, b3, acc[0][3]);
            acc[1][0] = ffma2(a.y, b0, acc[1][0]);
            acc[1][1] = ffma2(a.y, b1, acc[1][1]);
            acc[1][2] = ffma2(a.y, b2, acc[1][2]);
            acc[1][3] = ffma2(a.y, b3, acc[1][3]);
        }

        // unpack + scale (1/sqrt(64) = 0.125 exactly)
#pragma unroll
        for (int c = 0; c < 4; c++) {
            upk(acc[0][c], p[0][c], p[1][c]);
            upk(acc[1][c], p[2][c], p[3][c]);
        }
#pragma unroll
        for (int r = 0; r < 4; r++)
#pragma unroll
            for (int c = 0; c < 4; c++) p[r][c] *= 0.125f;

        // causal mask on the diagonal tile
        if (jt == qt) {
#pragma unroll
            for (int r = 0; r < 4; r++)
#pragma unroll
                for (int c = 0; c < 4; c++)
                    if (j0 + c > i0 + r) p[r][c] = -CUDART_INF_F;
        }

        float mnew[4], alpha[4];
#pragma unroll
        for (int r = 0; r < 4; r++) {
            float tm = fmaxf(fmaxf(p[r][0], p[r][1]), fmaxf(p[r][2], p[r][3]));
#pragma unroll
            for (int off = 1; off < 16; off <<= 1)
                tm = fmaxf(tm, __shfl_xor_sync(0xffffffffu, tm, off));
            mnew[r]  = fmaxf(m_r[r], tm);
            alpha[r] = __expf(m_r[r] - mnew[r]);
            float rs = 0.f;
#pragma unroll
            for (int c = 0; c < 4; c++) {
                p[r][c] = __expf(p[r][c] - mnew[r]);
                rs += p[r][c];
            }
#pragma unroll
            for (int off = 1; off < 16; off <<= 1)
                rs += __shfl_xor_sync(0xffffffffu, rs, off);
            l_r[r] = l_r[r] * alpha[r] + rs;
            m_r[r] = mnew[r];
        }
        {
            u64 av0 = pk(alpha[0], alpha[1]);
            u64 av1 = pk(alpha[2], alpha[3]);
#pragma unroll
            for (int c = 0; c < 4; c++) {
                Oac[0][c] = fmul2(av0, Oac[0][c]);
                Oac[1][c] = fmul2(av1, Oac[1][c]);
            }
        }

        // record running max for later fixup (uniform across tc; one writer)
        if (tc == 0) {
#pragma unroll
            for (int r = 0; r < 4; r++) mh[jt * BT + i0 + r] = mnew[r];
        }

        // stash p (transposed, j-major) for the PV gemm
#pragma unroll
        for (int r = 0; r < 4; r++)
#pragma unroll
            for (int c = 0; c < 4; c++)
                Ps[(j0 + c) * LDP + i0 + r] = p[r][c];

        // write UNNORMALIZED p for non-diagonal tiles (fixed up in epilogue)
        if (jt < qt) {
#pragma unroll
            for (int r = 0; r < 4; r++) {
                *(float4*)(Wb + (size_t)(qt * BT + i0 + r) * S_LEN + jt * BT + j0) =
                    make_float4(p[r][0], p[r][1], p[r][2], p[r][3]);
            }
        }

        __syncthreads();                 // Ps visible to all

        // ---- PV gemm: O[i][dd] += p[i][j] * V[j][dd] ----
#pragma unroll 16
        for (int j = 0; j < BT; j++) {
            ulonglong2 a = *(const ulonglong2*)(Ps + j * LDP + i0);  // p row-pairs at col j
            float4     b = *(const float4*)(Vs + j * LDP + j0);
            u64 b0 = pk(b.x, b.x), b1 = pk(b.y, b.y), b2 = pk(b.z, b.z), b3 = pk(b.w, b.w);
            Oac[0][0] = ffma2(a.x, b0, Oac[0][0]);
            Oac[0][1] = ffma2(a.x, b1, Oac[0][1]);
            Oac[0][2] = ffma2(a.x, b2, Oac[0][2]);
            Oac[0][3] = ffma2(a.x, b3, Oac[0][3]);
            Oac[1][0] = ffma2(a.y, b0, Oac[1][0]);
            Oac[1][1] = ffma2(a.y, b1, Oac[1][1]);
            Oac[1][2] = ffma2(a.y, b2, Oac[1][2]);
            Oac[1][3] = ffma2(a.y, b3, Oac[1][3]);
        }
    }

    float invl[4];
#pragma unroll
    for (int r = 0; r < 4; r++) invl[r] = 1.0f / l_r[r];

    // diagonal tile: p still holds jt==qt values, m there == m_final -> just /l
#pragma unroll
    for (int r = 0; r < 4; r++) {
        *(float4*)(Wb + (size_t)(qt * BT + i0 + r) * S_LEN + qt * BT + j0) =
            make_float4(p[r][0] * invl[r], p[r][1] * invl[r],
                        p[r][2] * invl[r], p[r][3] * invl[r]);
    }

    // attention output
    {
        float o[4][4];
#pragma unroll
        for (int c = 0; c < 4; c++) {
            upk(Oac[0][c], o[0][c], o[1][c]);
            upk(Oac[1][c], o[2][c], o[3][c]);
        }
#pragma unroll
        for (int r = 0; r < 4; r++) {
            *(float4*)(Ob + (i0 + r) * D_DIM + j0) =
                make_float4(o[r][0] * invl[r], o[r][1] * invl[r],
                            o[r][2] * invl[r], o[r][3] * invl[r]);
        }
    }

    __syncthreads();   // all mh writes visible for cross-thread reads below

    // fixup: rescale earlier tiles by exp(m_tile - m_final) / l
    for (int jt = 0; jt < qt; jt++) {
#pragma unroll
        for (int r = 0; r < 4; r++) {
            float f = __expf(mh[jt * BT + i0 + r] - m_r[r]) * invl[r];
            float* addr = Wb + (size_t)(qt * BT + i0 + r) * S_LEN + jt * BT + j0;
            float4 w = *(float4*)addr;
            w.x *= f; w.y *= f; w.z *= f; w.w *= f;
            *(float4*)addr = w;
        }
    }

    // zero-fill strict upper-triangle tiles
    float4 z = make_float4(0.f, 0.f, 0.f, 0.f);
    for (int jt = qt + 1; jt < NT; jt++) {
#pragma unroll
        for (int r = 0; r < 4; r++)
            *(float4*)(Wb + (size_t)(qt * BT + i0 + r) * S_LEN + jt * BT + j0) = z;
    }
}

extern "C" void kernel_launch(void* const* d_in, const int* in_sizes, int n_in,
                              void* d_out, int out_size) {
    (void)in_sizes; (void)n_in; (void)out_size;
    const float* q = (const float*)d_in[0];
    const float* k = (const float*)d_in[1];
    const float* v = (const float*)d_in[2];
    // d_in[3] is the mask (tril ones) — causal structure applied analytically.

    float* out = (float*)d_out;
    float* Og  = out;                                   // [B,H,S,D] = 4,194,304 floats
    float* Wg  = out + (size_t)BH * S_LEN * D_DIM;      // [B,H,S,S] follows

    cudaFuncSetAttribute(sdpa_causal_kernel,
                         cudaFuncAttributeMaxDynamicSharedMemorySize, SMEM_BYTES);

    dim3 grid(NT, BH);
    sdpa_causal_kernel<<<grid, 256, SMEM_BYTES>>>(q, k, v, Og, Wg);
}

// round 15
// speedup vs baseline: 1.5292x; 1.1048x over previous
#include <cuda_runtime.h>
#include <math_constants.h>

// Problem constants (B=2, H=16, S=2048, D=64)
#define S_LEN 2048
#define D_DIM 64
#define BH    32
#define BQ    128             // CTA tile: 128 q-rows x 128 k-cols
#define NTQ   (S_LEN / BQ)    // 16 tiles
#define PQ    132             // pitch (floats) for Qs/Ks/Ps
#define PVP   68              // pitch (floats) for Vs

// smem layout (floats)
#define SM_KS (64 * PQ)
#define SM_VS (SM_KS + 64 * PQ)
#define SM_PS (SM_VS + 128 * PVP)
#define SM_MH (SM_PS + 128 * PQ)
#define SMEM_FLOATS (SM_MH + NTQ * BQ)
#define SMEM_BYTES  (SMEM_FLOATS * 4)   // 178176 bytes

typedef unsigned long long u64;

// ---------- packed f32x2 helpers (Blackwell sm_103a) ----------
__device__ __forceinline__ u64 pk(float lo, float hi) {
    u64 r; asm("mov.b64 %0, {%1,%2};" : "=l"(r) : "f"(lo), "f"(hi)); return r;
}
__device__ __forceinline__ void upk(u64 v, float& lo, float& hi) {
    asm("mov.b64 {%0,%1}, %2;" : "=f"(lo), "=f"(hi) : "l"(v));
}
__device__ __forceinline__ u64 ffma2(u64 a, u64 b, u64 c) {
    u64 d; asm("fma.rn.f32x2 %0, %1, %2, %3;" : "=l"(d) : "l"(a), "l"(b), "l"(c)); return d;
}
__device__ __forceinline__ u64 fmul2(u64 a, u64 b) {
    u64 d; asm("mul.rn.f32x2 %0, %1, %2;" : "=l"(d) : "l"(a), "l"(b)); return d;
}

// 128x64 gmem tile -> d-major smem (transposed) with 2-bit XOR row-block swizzle.
// sm[d*PQ + ((row>>3 ^ ((d>>2)&3))<<3) + (row&7)]
__device__ __forceinline__ void load_tileT(const float* __restrict__ g, float* sm, int tid) {
#pragma unroll
    for (int it = 0; it < 8; it++) {
        int idx = tid + 256 * it;
        int row = idx >> 4;
        int dq  = (idx & 15) << 2;
        float4 v = *(const float4*)(g + row * D_DIM + dq);
        int key  = (dq >> 2) & 3;             // same for d = dq..dq+3
        int base = (((row >> 3) ^ key) << 3) + (row & 7);
        sm[(dq + 0) * PQ + base] = v.x;
        sm[(dq + 1) * PQ + base] = v.y;
        sm[(dq + 2) * PQ + base] = v.z;
        sm[(dq + 3) * PQ + base] = v.w;
    }
}

// 128x64 gmem tile -> row-major smem with 3-bit XOR col-block swizzle.
// sm[j*PVP + ((dq>>3 ^ (j&7))<<3) + (dq&7)]
__device__ __forceinline__ void load_tileV(const float* __restrict__ g, float* sm, int tid) {
#pragma unroll
    for (int it = 0; it < 8; it++) {
        int idx = tid + 256 * it;
        int row = idx >> 4;
        int dq  = (idx & 15) << 2;
        float4 v = *(const float4*)(g + row * D_DIM + dq);
        int phys = ((((dq >> 3) ^ (row & 7))) << 3) + (dq & 7);
        *(float4*)(sm + row * PVP + phys) = v;
    }
}

__global__ void __launch_bounds__(256, 1)
sdpa_causal_kernel(const float* __restrict__ Qg, const float* __restrict__ Kg,
                   const float* __restrict__ Vg, float* __restrict__ Og,
                   float* __restrict__ Wg)
{
    extern __shared__ float sm[];
    float* Qs = sm;                 // [64][PQ] d-major, swizzled
    float* Ks = sm + SM_KS;         // [64][PQ] d-major, swizzled
    float* Vs = sm + SM_VS;         // [128][PVP] j-major, swizzled
    float* Ps = sm + SM_PS;         // [128][PQ] j-major (p transposed), swizzled
    float* mh = sm + SM_MH;         // [NTQ][BQ] running-max history

    const int qt  = (NTQ - 1) - blockIdx.x;   // heavy tiles first (LPT)
    const int bh  = blockIdx.y;
    const int tid = threadIdx.x;
    const int tr  = tid >> 4;                 // 0..15 -> q-row group
    const int tc  = tid & 15;                 // 0..15 -> col group
    const int i0  = tr * 8;
    const int jA  = tc * 4;                   // owned cols jA..jA+3, jB..jB+3
    const int jB  = 64 + tc * 4;

    const float* Qb = Qg + (size_t)bh * S_LEN * D_DIM + (size_t)qt * BQ * D_DIM;
    const float* Kb = Kg + (size_t)bh * S_LEN * D_DIM;
    const float* Vb = Vg + (size_t)bh * S_LEN * D_DIM;
    float*       Ob = Og + (size_t)bh * S_LEN * D_DIM + (size_t)qt * BQ * D_DIM;
    float*       Wb = Wg + (size_t)bh * S_LEN * S_LEN;

    load_tileT(Qb, Qs, tid);

    float m_r[8], l_r[8];
#pragma unroll
    for (int r = 0; r < 8; r++) { m_r[r] = -CUDART_INF_F; l_r[r] = 0.f; }

    u64 Oac[4][8];                            // 8 rows (pairs) x 8 dd, partial over j-half
#pragma unroll
    for (int rp = 0; rp < 4; rp++)
#pragma unroll
        for (int c = 0; c < 8; c++) Oac[rp][c] = 0ull;

    const int jbase = (tc >> 3) << 6;         // PV j-half: 0 or 64
    const int dd0   = (tc & 7) << 3;          // PV dd block

    float p[8][8];                            // exp(scores) of current tile

    for (int jt = 0; jt <= qt; jt++) {
        __syncthreads();                      // prev PV done with Ks/Vs/Ps
        load_tileT(Kb + (size_t)jt * BQ * D_DIM, Ks, tid);
        load_tileV(Vb + (size_t)jt * BQ * D_DIM, Vs, tid);
        __syncthreads();

        // ---------------- QK^T: 8x8 micro-tile ----------------
        u64 acc[4][8];
#pragma unroll
        for (int rp = 0; rp < 4; rp++)
#pragma unroll
            for (int c = 0; c < 8; c++) acc[rp][c] = 0ull;

#pragma unroll 4
        for (int d = 0; d < D_DIM; d++) {
            int key = (d >> 2) & 3;
            const float* qrow = Qs + d * PQ + ((tr ^ key) << 3);
            ulonglong2 a01 = *(const ulonglong2*)qrow;        // rows i0..i0+3
            ulonglong2 a23 = *(const ulonglong2*)(qrow + 4);  // rows i0+4..i0+7
            const float* krow = Ks + d * PQ + ((((tc >> 1) ^ key)) << 3) + ((tc & 1) << 2);
            float4 b0 = *(const float4*)krow;                 // cols jA..jA+3
            float4 b1 = *(const float4*)(krow + 64);          // cols jB..jB+3
            u64 aa[4] = {a01.x, a01.y, a23.x, a23.y};
            u64 bb[8] = {pk(b0.x,b0.x), pk(b0.y,b0.y), pk(b0.z,b0.z), pk(b0.w,b0.w),
                         pk(b1.x,b1.x), pk(b1.y,b1.y), pk(b1.z,b1.z), pk(b1.w,b1.w)};
#pragma unroll
            for (int rp = 0; rp < 4; rp++)
#pragma unroll
                for (int c = 0; c < 8; c++)
                    acc[rp][c] = ffma2(aa[rp], bb[c], acc[rp][c]);
        }

        // unpack + scale (1/sqrt(64) = 0.125 exact)
#pragma unroll
        for (int rp = 0; rp < 4; rp++)
#pragma unroll
            for (int c = 0; c < 8; c++)
                upk(acc[rp][c], p[2*rp][c], p[2*rp+1][c]);
#pragma unroll
        for (int r = 0; r < 8; r++)
#pragma unroll
            for (int c = 0; c < 8; c++) p[r][c] *= 0.125f;

        // causal mask on diagonal tile
        if (jt == qt) {
#pragma unroll
            for (int r = 0; r < 8; r++)
#pragma unroll
                for (int c = 0; c < 8; c++) {
                    int col = (c < 4) ? (jA + c) : (jB + c - 4);
                    if (col > i0 + r) p[r][c] = -CUDART_INF_F;
                }
        }

        // ---------------- online softmax ----------------
        float mnew[8], alpha[8];
#pragma unroll
        for (int r = 0; r < 8; r++) {
            float tm = p[r][0];
#pragma unroll
            for (int c = 1; c < 8; c++) tm = fmaxf(tm, p[r][c]);
#pragma unroll
            for (int off = 1; off < 16; off <<= 1)
                tm = fmaxf(tm, __shfl_xor_sync(0xffffffffu, tm, off));
            mnew[r]  = fmaxf(m_r[r], tm);
            alpha[r] = __expf(m_r[r] - mnew[r]);
            float rs = 0.f;
#pragma unroll
            for (int c = 0; c < 8; c++) { p[r][c] = __expf(p[r][c] - mnew[r]); rs += p[r][c]; }
#pragma unroll
            for (int off = 1; off < 16; off <<= 1)
                rs += __shfl_xor_sync(0xffffffffu, rs, off);
            l_r[r] = l_r[r] * alpha[r] + rs;
            m_r[r] = mnew[r];
        }
        {
            u64 av[4] = {pk(alpha[0],alpha[1]), pk(alpha[2],alpha[3]),
                         pk(alpha[4],alpha[5]), pk(alpha[6],alpha[7])};
#pragma unroll
            for (int rp = 0; rp < 4; rp++)
#pragma unroll
                for (int c = 0; c < 8; c++)
                    Oac[rp][c] = fmul2(av[rp], Oac[rp][c]);
        }

        if (tc == 0) {
#pragma unroll
            for (int r = 0; r < 8; r++) mh[jt * BQ + i0 + r] = mnew[r];
        }

        // stash p transposed (j-major, swizzled) for PV
#pragma unroll
        for (int cc = 0; cc < 4; cc++) {
            // col jA+cc : key = (j>>2)&3 = tc&3
            float* dst = Ps + (jA + cc) * PQ + ((tr ^ (tc & 3)) << 3);
            *(float4*)dst       = make_float4(p[0][cc], p[1][cc], p[2][cc], p[3][cc]);
            *(float4*)(dst + 4) = make_float4(p[4][cc], p[5][cc], p[6][cc], p[7][cc]);
            float* dst2 = Ps + (jB + cc) * PQ + ((tr ^ (tc & 3)) << 3);
            *(float4*)dst2       = make_float4(p[0][cc+4], p[1][cc+4], p[2][cc+4], p[3][cc+4]);
            *(float4*)(dst2 + 4) = make_float4(p[4][cc+4], p[5][cc+4], p[6][cc+4], p[7][cc+4]);
        }

        // write UNNORMALIZED p for non-diagonal tiles (fixed up in epilogue)
        if (jt < qt) {
#pragma unroll
            for (int r = 0; r < 8; r++) {
                float* wrow = Wb + (size_t)(qt * BQ + i0 + r) * S_LEN + jt * BQ;
                *(float4*)(wrow + jA) = make_float4(p[r][0], p[r][1], p[r][2], p[r][3]);
                *(float4*)(wrow + jB) = make_float4(p[r][4], p[r][5], p[r][6], p[r][7]);
            }
        }

        __syncthreads();   // Ps visible

        // ---------------- PV: split j-range, 8x8 partials ----------------
#pragma unroll 4
        for (int jj = 0; jj < 64; jj++) {
            int j = jbase + jj;
            int keyp = (j >> 2) & 3;
            const float* prow = Ps + j * PQ + ((tr ^ keyp) << 3);
            ulonglong2 a01 = *(const ulonglong2*)prow;
            ulonglong2 a23 = *(const ulonglong2*)(prow + 4);
            const float* vrow = Vs + j * PVP + ((((tc & 7) ^ (j & 7))) << 3);
            float4 b0 = *(const float4*)vrow;        // dd0..dd0+3
            float4 b1 = *(const float4*)(vrow + 4);  // dd0+4..dd0+7
            u64 aa[4] = {a01.x, a01.y, a23.x, a23.y};
            u64 bb[8] = {pk(b0.x,b0.x), pk(b0.y,b0.y), pk(b0.z,b0.z), pk(b0.w,b0.w),
                         pk(b1.x,b1.x), pk(b1.y,b1.y), pk(b1.z,b1.z), pk(b1.w,b1.w)};
#pragma unroll
            for (int rp = 0; rp < 4; rp++)
#pragma unroll
                for (int c = 0; c < 8; c++)
                    Oac[rp][c] = ffma2(aa[rp], bb[c], Oac[rp][c]);
        }
    }

    float invl[8];
#pragma unroll
    for (int r = 0; r < 8; r++) invl[r] = 1.0f / l_r[r];

    // diagonal tile: p still holds jt==qt values (m there == m_final) -> just /l
#pragma unroll
    for (int r = 0; r < 8; r++) {
        float* wrow = Wb + (size_t)(qt * BQ + i0 + r) * S_LEN + qt * BQ;
        *(float4*)(wrow + jA) = make_float4(p[r][0]*invl[r], p[r][1]*invl[r],
                                            p[r][2]*invl[r], p[r][3]*invl[r]);
        *(float4*)(wrow + jB) = make_float4(p[r][4]*invl[r], p[r][5]*invl[r],
                                            p[r][6]*invl[r], p[r][7]*invl[r]);
    }

    // ---------------- combine O partials across j-halves ----------------
    __syncthreads();   // PV done with Vs everywhere; reuse Vs as scratch
    if (tc >= 8) {
#pragma unroll
        for (int rp = 0; rp < 4; rp++) {
            float o0[8], o1[8];
#pragma unroll
            for (int c = 0; c < 8; c++) upk(Oac[rp][c], o0[c], o1[c]);
            float* s0 = Vs + (i0 + 2*rp)     * PVP + dd0;
            float* s1 = Vs + (i0 + 2*rp + 1) * PVP + dd0;
            *(float4*)s0       = make_float4(o0[0], o0[1], o0[2], o0[3]);
            *(float4*)(s0 + 4) = make_float4(o0[4], o0[5], o0[6], o0[7]);
            *(float4*)s1       = make_float4(o1[0], o1[1], o1[2], o1[3]);
            *(float4*)(s1 + 4) = make_float4(o1[4], o1[5], o1[6], o1[7]);
        }
    }
    __syncthreads();
    if (tc < 8) {
#pragma unroll
        for (int rp = 0; rp < 4; rp++) {
            float o0[8], o1[8];
#pragma unroll
            for (int c = 0; c < 8; c++) upk(Oac[rp][c], o0[c], o1[c]);
            const float* s0 = Vs + (i0 + 2*rp)     * PVP + dd0;
            const float* s1 = Vs + (i0 + 2*rp + 1) * PVP + dd0;
            float4 q0 = *(const float4*)s0, q1 = *(const float4*)(s0 + 4);
            float4 q2 = *(const float4*)s1, q3 = *(const float4*)(s1 + 4);
            float il0 = invl[2*rp], il1 = invl[2*rp+1];
            *(float4*)(Ob + (i0 + 2*rp) * D_DIM + dd0) =
                make_float4((o0[0]+q0.x)*il0, (o0[1]+q0.y)*il0, (o0[2]+q0.z)*il0, (o0[3]+q0.w)*il0);
            *(float4*)(Ob + (i0 + 2*rp) * D_DIM + dd0 + 4) =
                make_float4((o0[4]+q1.x)*il0, (o0[5]+q1.y)*il0, (o0[6]+q1.z)*il0, (o0[7]+q1.w)*il0);
            *(float4*)(Ob + (i0 + 2*rp + 1) * D_DIM + dd0) =
                make_float4((o1[0]+q2.x)*il1, (o1[1]+q2.y)*il1, (o1[2]+q2.z)*il1, (o1[3]+q2.w)*il1);
            *(float4*)(Ob + (i0 + 2*rp + 1) * D_DIM + dd0 + 4) =
                make_float4((o1[4]+q3.x)*il1, (o1[5]+q3.y)*il1, (o1[6]+q3.z)*il1, (o1[7]+q3.w)*il1);
        }
    }

    // ---------------- W fixup: rescale earlier tiles ----------------
    for (int jt = 0; jt < qt; jt++) {
#pragma unroll
        for (int r = 0; r < 8; r++) {
            float f = __expf(mh[jt * BQ + i0 + r] - m_r[r]) * invl[r];
            float* wrow = Wb + (size_t)(qt * BQ + i0 + r) * S_LEN + jt * BQ;
            float4 w0 = *(float4*)(wrow + jA);
            float4 w1 = *(float4*)(wrow + jB);
            w0.x *= f; w0.y *= f; w0.z *= f; w0.w *= f;
            w1.x *= f; w1.y *= f; w1.z *= f; w1.w *= f;
            *(float4*)(wrow + jA) = w0;
            *(float4*)(wrow + jB) = w1;
        }
    }

    // ---------------- zero-fill strict upper-triangle tiles ----------------
    float4 z = make_float4(0.f, 0.f, 0.f, 0.f);
    for (int jt = qt + 1; jt < NTQ; jt++) {
#pragma unroll
        for (int r = 0; r < 8; r++) {
            float* wrow = Wb + (size_t)(qt * BQ + i0 + r) * S_LEN + jt * BQ;
            *(float4*)(wrow + jA) = z;
            *(float4*)(wrow + jB) = z;
        }
    }
}

extern "C" void kernel_launch(void* const* d_in, const int* in_sizes, int n_in,
                              void* d_out, int out_size) {
    (void)in_sizes; (void)n_in; (void)out_size;
    const float* q = (const float*)d_in[0];
    const float* k = (const float*)d_in[1];
    const float* v = (const float*)d_in[2];
    // d_in[3] is the mask (tril ones) — causal structure applied analytically.

    float* out = (float*)d_out;
    float* Og  = out;                                   // [B,H,S,D]
    float* Wg  = out + (size_t)BH * S_LEN * D_DIM;      // [B,H,S,S]

    cudaFuncSetAttribute(sdpa_causal_kernel,
                         cudaFuncAttributeMaxDynamicSharedMemorySize, SMEM_BYTES);

    dim3 grid(NTQ, BH);
    sdpa_causal_kernel<<<grid, 256, SMEM_BYTES>>>(q, k, v, Og, Wg);
}